// round 7
// baseline (speedup 1.0000x reference)
#include <cuda_runtime.h>
#include <cuda_bf16.h>
#include <math.h>
#include <float.h>
#include <stdint.h>

// Problem constants
#define DDIM 256
#define KCODE 1024
#define HW 4096
#define NPOS 65536
#define ZQ_ELEMS 16777216

// Screening margin: reference's final subtract quantizes dv on a grid of
// ulp(~256)=3.05e-5; bf16-split TC dot error ~1e-7..1e-6 << grid. Gap > 2 grid
// steps + slack  =>  argmin provably identical to the reference's.
#define DELTA_GAP 8e-5f

__device__ float  g_b[KCODE];
__device__ float  g_a[NPOS];
__device__ int    g_idx[NPOS];
__device__ int    g_flag[NPOS];
__device__ int    g_cnt;
__device__ double g_loss;
__device__ __align__(16) __nv_bfloat16 g_eh[KCODE * DDIM];
__device__ __align__(16) __nv_bfloat16 g_el[KCODE * DDIM];
// Per-k-half partial argmin state: [half][n]
__device__ float g_m1[2 * NPOS];
__device__ float g_m2[2 * NPOS];
__device__ int   g_k1[2 * NPOS];

// ---------------------------------------------------------------------------
// PTX helpers — all sm_80-class features, valid on plain sm_103 target
// ---------------------------------------------------------------------------
__device__ __forceinline__ unsigned stu32(const void* p) {
    return (unsigned)__cvta_generic_to_shared(p);
}
__device__ __forceinline__ void cp16(unsigned dst, const void* src) {
    asm volatile("cp.async.cg.shared.global [%0], [%1], 16;" :: "r"(dst), "l"(src));
}
__device__ __forceinline__ void cp_commit() { asm volatile("cp.async.commit_group;"); }
__device__ __forceinline__ void cp_wait1()  { asm volatile("cp.async.wait_group 1;"); }
__device__ __forceinline__ void cp_wait0()  { asm volatile("cp.async.wait_group 0;"); }

__device__ __forceinline__ void ldm4(unsigned* r, unsigned addr) {
    asm volatile("ldmatrix.sync.aligned.m8n8.x4.shared.b16 {%0,%1,%2,%3}, [%4];"
        : "=r"(r[0]), "=r"(r[1]), "=r"(r[2]), "=r"(r[3]) : "r"(addr));
}
__device__ __forceinline__ void mma16816(float* c, const unsigned* a,
                                         unsigned b0, unsigned b1) {
    asm volatile(
        "mma.sync.aligned.m16n8k16.row.col.f32.bf16.bf16.f32 "
        "{%0,%1,%2,%3}, {%4,%5,%6,%7}, {%8,%9}, {%0,%1,%2,%3};"
        : "+f"(c[0]), "+f"(c[1]), "+f"(c[2]), "+f"(c[3])
        : "r"(a[0]), "r"(a[1]), "r"(a[2]), "r"(a[3]), "r"(b0), "r"(b1));
}

// ---------------------------------------------------------------------------
// emb prep: exact b_k (same order as the rel_err=0.0 kernels) + bf16 split.
// Also zeroes the loss/flag accumulators (replay-safe).
// ---------------------------------------------------------------------------
__global__ void k_prep(const float* __restrict__ emb) {
    if (blockIdx.x == 0 && threadIdx.x == 0) { g_loss = 0.0; g_cnt = 0; }
    int warp = blockIdx.x * (blockDim.x >> 5) + (threadIdx.x >> 5);
    int lane = threadIdx.x & 31;
    if (warp >= KCODE) return;
    const float* row = emb + (size_t)warp * DDIM;
    float s = 0.f;
    #pragma unroll
    for (int d = lane; d < DDIM; d += 32) { float v = row[d]; s = fmaf(v, v, s); }
    #pragma unroll
    for (int o = 16; o; o >>= 1) s += __shfl_xor_sync(0xffffffffu, s, o);
    if (lane == 0) g_b[warp] = s;

    __align__(16) __nv_bfloat16 h[8], l[8];
    int base = lane * 8;
    #pragma unroll
    for (int q = 0; q < 8; ++q) {
        float v = row[base + q];
        h[q] = __float2bfloat16(v);
        l[q] = __float2bfloat16(v - __bfloat162float(h[q]));
    }
    *reinterpret_cast<uint4*>(&g_eh[warp * DDIM + base]) = *reinterpret_cast<uint4*>(h);
    *reinterpret_cast<uint4*>(&g_el[warp * DDIM + base]) = *reinterpret_cast<uint4*>(l);
}

// ---------------------------------------------------------------------------
// HMMA screening kernel: CTA = 128 n x 512 codes (k-half split -> 1024 CTAs,
// 6.92 waves: kills the 4-vs-3.46 wave quantization of the 512-CTA layout).
// Prologue stages this CTA's z slice (fp32) into the B region, transposes +
// bf16-splits into A smem, computes exact a_n (sequential ascending d).
// Mainloop: c = zh*eh (acc Ch) + zh*el + zl*eh (acc Cl); explicit 2-stage
// ldmatrix register pipeline hides LDS latency at 2 warps/SMSP.
// Writes per-half (m1, m2, k1) partials; k_merge does the gap test.
// smem pitch: 528 B rows (odd x 16B -> ldmatrix conflict-free).
// ---------------------------------------------------------------------------
#define ROWB 528
#define OFF_AH 0
#define OFF_AL 67584            /* 128*528 */
#define OFF_B  135168           /* 2 bufs x (Bh 16896 + Bl 16896); also z stage */
#define OFF_BS 202752           /* 512 floats (this half's b_k) */
#define OFF_AS 206848           /* 128 floats */
#define SM_TOTAL 207360
#define PSTG 132                /* z stage pitch in floats (= 528 B) */
#define NCH 16                  /* 16 chunks x 32 codes = 512 codes per CTA */

extern __shared__ char sm_raw[];

__global__ void __launch_bounds__(256, 1)
k_mma(const float* __restrict__ z) {
    unsigned sb = stu32(sm_raw);
    const int tid = threadIdx.x;
    const int lane = tid & 31, w = tid >> 5;         // w = n-tile 0..7
    const int tile = blockIdx.x >> 1;
    const int half = blockIdx.x & 1;
    const int n0 = tile * 128;
    const int kbase = half * 512;

    // ---------- Prologue: stage z (fp32) -> split into Ah/Al + exact a_n ----
    float* stg = (float*)(sm_raw + OFF_B);           // [128 d][PSTG] fp32
    const int b = n0 >> 12, hw0 = n0 & 4095;
    const float* zb = z + ((size_t)b << 20) + hw0;   // contiguous 128 n per CTA
    float a_acc = 0.f;

    #pragma unroll
    for (int c = 0; c < 2; ++c) {
        for (int i = tid; i < 128 * 32; i += 256) {
            int d = i >> 5, j = i & 31;
            cp16(sb + OFF_B + d * ROWB + j * 16,
                 zb + (size_t)(c * 128 + d) * HW + j * 4);
        }
        cp_commit(); cp_wait0();
        __syncthreads();
        {
            int nn = tid >> 1, hf = tid & 1;
            unsigned dstA = (unsigned)(nn * ROWB + c * 256 + hf * 128);
            #pragma unroll
            for (int g = 0; g < 8; ++g) {
                __align__(16) __nv_bfloat16 hh[8], ll[8];
                #pragma unroll
                for (int q = 0; q < 8; ++q) {
                    float v = stg[(hf * 64 + g * 8 + q) * PSTG + nn];
                    hh[q] = __float2bfloat16(v);
                    ll[q] = __float2bfloat16(v - __bfloat162float(hh[q]));
                }
                *(uint4*)(sm_raw + OFF_AH + dstA + g * 16) = *(uint4*)hh;
                *(uint4*)(sm_raw + OFF_AL + dstA + g * 16) = *(uint4*)ll;
            }
        }
        if (tid < 128) {
            #pragma unroll 4
            for (int dl = 0; dl < 128; ++dl) {
                float v = stg[dl * PSTG + tid];
                a_acc = fmaf(v, v, a_acc);
            }
        }
        __syncthreads();                              // stage consumed
    }

    float* bsm  = (float*)(sm_raw + OFF_BS);
    float* asm_ = (float*)(sm_raw + OFF_AS);
    if (tid < 128) {
        asm_[tid] = a_acc;
        if (half == 0) g_a[n0 + tid] = a_acc;
    }
    for (int i = tid; i < 512; i += 256) bsm[i] = g_b[kbase + i];

    // ---------- B pipeline (this half's 512 codes, 16 chunks of 32) --------
    auto prefB = [&](int c) {
        unsigned bufh = sb + OFF_B + (c & 1) * 33792;
        const char* eh = (const char*)g_eh;
        const char* el = (const char*)g_el;
        for (int u = tid; u < 32 * 32; u += 256) {
            int r = u >> 5, j = u & 31;
            size_t src = (size_t)(kbase + c * 32 + r) * 512 + j * 16;
            unsigned dst = r * ROWB + j * 16;
            cp16(bufh + dst, eh + src);
            cp16(bufh + 16896 + dst, el + src);
        }
    };
    prefB(0); cp_commit();
    prefB(1); cp_commit();
    __syncthreads();            // asm_/bsm visible

    const int grp = lane >> 3, ii = lane & 7;
    const unsigned aOff = (unsigned)((w * 16 + ((grp & 1) ? 8 : 0) + ii) * ROWB
                                     + ((grp & 2) ? 16 : 0));
    const unsigned bOff = (unsigned)((((grp >> 1) ? 8 : 0) + ii) * ROWB
                                     + ((grp & 1) ? 16 : 0));

    const float aA = asm_[w * 16 + (lane >> 2)];
    const float aB = asm_[w * 16 + (lane >> 2) + 8];
    float m1A = FLT_MAX, m2A = FLT_MAX, m1B = FLT_MAX, m2B = FLT_MAX;
    int k1A = kbase, k1B = kbase;

    #define UPD(m1, m2, k1, dv, k) \
        { if ((dv) < (m1)) { (m2) = (m1); (m1) = (dv); (k1) = (k); } \
          else if ((dv) < (m2)) (m2) = (dv); }

    for (int c = 0; c < NCH; ++c) {
        if (c == NCH - 1) cp_wait0(); else cp_wait1();   // B(c) resident
        __syncthreads();

        unsigned bufh = sb + OFF_B + (c & 1) * 33792;
        const unsigned pAh = sb + OFF_AH + aOff;
        const unsigned pAl = sb + OFF_AL + aOff;
        const unsigned pH0 = bufh + bOff;                // eh codes 0-15
        const unsigned pH1 = bufh + 16 * ROWB + bOff;    // eh codes 16-31
        const unsigned pL0 = bufh + 16896 + bOff;        // el codes 0-15
        const unsigned pL1 = bufh + 16896 + 16 * ROWB + bOff;

        float Ch[4][4], Cl[4][4];
        #pragma unroll
        for (int t = 0; t < 4; ++t)
            #pragma unroll
            for (int q = 0; q < 4; ++q) { Ch[t][q] = 0.f; Cl[t][q] = 0.f; }

        // 2-stage register pipeline: fragments for step s+1 load during the
        // 12 MMAs of step s (hides LDS latency at low occupancy).
        unsigned R[2][24];
        {
            unsigned* r = R[0];
            ldm4(r + 0,  pAh); ldm4(r + 4,  pAl);
            ldm4(r + 8,  pH0); ldm4(r + 12, pH1);
            ldm4(r + 16, pL0); ldm4(r + 20, pL1);
        }
        #pragma unroll
        for (int s = 0; s < 16; ++s) {
            if (s < 15) {
                unsigned o = (unsigned)(s + 1) * 32;
                unsigned* r = R[(s + 1) & 1];
                ldm4(r + 0,  pAh + o); ldm4(r + 4,  pAl + o);
                ldm4(r + 8,  pH0 + o); ldm4(r + 12, pH1 + o);
                ldm4(r + 16, pL0 + o); ldm4(r + 20, pL1 + o);
            }
            const unsigned* r = R[s & 1];
            const unsigned* Ah = r + 0;  const unsigned* Al = r + 4;
            const unsigned* B0 = r + 8;  const unsigned* B1 = r + 12;
            const unsigned* B2 = r + 16; const unsigned* B3 = r + 20;
            mma16816(Cl[0], Ah, B2[0], B2[1]);   // zh*el
            mma16816(Cl[1], Ah, B2[2], B2[3]);
            mma16816(Cl[2], Ah, B3[0], B3[1]);
            mma16816(Cl[3], Ah, B3[2], B3[3]);
            mma16816(Ch[0], Ah, B0[0], B0[1]);   // zh*eh
            mma16816(Ch[1], Ah, B0[2], B0[3]);
            mma16816(Ch[2], Ah, B1[0], B1[1]);
            mma16816(Ch[3], Ah, B1[2], B1[3]);
            mma16816(Cl[0], Al, B0[0], B0[1]);   // zl*eh
            mma16816(Cl[1], Al, B0[2], B0[3]);
            mma16816(Cl[2], Al, B1[0], B1[1]);
            mma16816(Cl[3], Al, B1[2], B1[3]);
        }

        __syncthreads();                             // all warps done with buf
        if (c + 2 < NCH) { prefB(c + 2); cp_commit(); }

        int kl = c * 32 + (lane & 3) * 2;            // local k within half
        #pragma unroll
        for (int t = 0; t < 4; ++t) {
            int kc = kl + t * 8;
            float b0 = bsm[kc], b1 = bsm[kc + 1];
            float c00 = Ch[t][0] + Cl[t][0];
            float c01 = Ch[t][1] + Cl[t][1];
            float c10 = Ch[t][2] + Cl[t][2];
            float c11 = Ch[t][3] + Cl[t][3];
            float d0 = fmaf(-2.f, c00, aA + b0);
            float d1 = fmaf(-2.f, c01, aA + b1);
            float d2 = fmaf(-2.f, c10, aB + b0);
            float d3 = fmaf(-2.f, c11, aB + b1);
            int kg = kbase + kc;
            UPD(m1A, m2A, k1A, d0, kg);
            UPD(m1A, m2A, k1A, d1, kg + 1);
            UPD(m1B, m2B, k1B, d2, kg);
            UPD(m1B, m2B, k1B, d3, kg + 1);
        }
    }

    // Reduce across the 4 lanes sharing each row (lex (dv,k); true 2nd-min)
    #pragma unroll
    for (int o = 1; o <= 2; o <<= 1) {
        float om1 = __shfl_xor_sync(0xffffffffu, m1A, o);
        int   ok1 = __shfl_xor_sync(0xffffffffu, k1A, o);
        float om2 = __shfl_xor_sync(0xffffffffu, m2A, o);
        bool take = (om1 < m1A) || (om1 == m1A && ok1 < k1A);
        m2A = fminf(fminf(m2A, om2), take ? m1A : om1);
        if (take) { m1A = om1; k1A = ok1; }

        om1 = __shfl_xor_sync(0xffffffffu, m1B, o);
        ok1 = __shfl_xor_sync(0xffffffffu, k1B, o);
        om2 = __shfl_xor_sync(0xffffffffu, m2B, o);
        take = (om1 < m1B) || (om1 == m1B && ok1 < k1B);
        m2B = fminf(fminf(m2B, om2), take ? m1B : om1);
        if (take) { m1B = om1; k1B = ok1; }
    }
    if ((lane & 3) == 0) {
        int nA = n0 + w * 16 + (lane >> 2);
        int sA = half * NPOS + nA;
        g_m1[sA] = m1A; g_m2[sA] = m2A; g_k1[sA] = k1A;
        int sB = sA + 8;
        g_m1[sB] = m1B; g_m2[sB] = m2B; g_k1[sB] = k1B;
    }
}

// ---------------------------------------------------------------------------
// Merge the two k-halves, run the provable-gap test, flag ambiguous positions.
// ---------------------------------------------------------------------------
__global__ void k_merge() {
    int n = blockIdx.x * blockDim.x + threadIdx.x;
    if (n >= NPOS) return;
    float m1a = g_m1[n],        m2a = g_m2[n];        int k1a = g_k1[n];
    float m1b = g_m1[NPOS + n], m2b = g_m2[NPOS + n]; int k1b = g_k1[NPOS + n];
    bool bwin = (m1b < m1a);                 // tie -> half A (lower k)
    float m1 = bwin ? m1b : m1a;
    int   k1 = bwin ? k1b : k1a;
    float m2 = fminf(fminf(m2a, m2b), bwin ? m1a : m1b);
    if (m2 - m1 > DELTA_GAP) g_idx[n] = k1;
    else g_flag[atomicAdd(&g_cnt, 1)] = n;
}

// ---------------------------------------------------------------------------
// Exact fallback: bit-identical fp32 full scan for flagged positions only.
// ---------------------------------------------------------------------------
__global__ __launch_bounds__(256)
void k_exact(const float* __restrict__ z, const float* __restrict__ emb) {
    __shared__ float zs[8][257];
    __shared__ float es[32][257];
    __shared__ int ns[8];
    __shared__ float aa[8];
    int tx = threadIdx.x & 31, ty = threadIdx.x >> 5;

    for (int base = blockIdx.x * 8; base < g_cnt; base += gridDim.x * 8) {
        int cnt = g_cnt;
        if (threadIdx.x < 8) {
            int v = (base + threadIdx.x < cnt) ? g_flag[base + threadIdx.x] : -1;
            ns[threadIdx.x] = v;
            aa[threadIdx.x] = (v >= 0) ? g_a[v] : 0.f;
        }
        __syncthreads();
        for (int i = threadIdx.x; i < 8 * 256; i += 256) {
            int sl = i >> 8, d = i & 255;
            int nn = ns[sl];
            zs[sl][d] = (nn >= 0)
                ? z[((size_t)(nn >> 12) << 20) + ((size_t)d << 12) + (nn & 4095)] : 0.f;
        }
        float m1 = FLT_MAX; int k1 = 0;
        for (int c0 = 0; c0 < KCODE; c0 += 32) {
            __syncthreads();
            for (int i = threadIdx.x; i < 32 * 256; i += 256) {
                int r = i >> 8, d = i & 255;
                es[r][d] = emb[(size_t)(c0 + r) * DDIM + d];
            }
            __syncthreads();
            float c = 0.f;
            const float* zr = zs[ty];
            const float* er = es[tx];
            #pragma unroll 4
            for (int d = 0; d < DDIM; ++d) c = fmaf(zr[d], er[d], c);
            float dv = fmaf(-2.0f, c, aa[ty] + g_b[c0 + tx]);
            if (dv < m1) { m1 = dv; k1 = c0 + tx; }
        }
        #pragma unroll
        for (int o = 16; o; o >>= 1) {
            float ov = __shfl_xor_sync(0xffffffffu, m1, o);
            int   ok = __shfl_xor_sync(0xffffffffu, k1, o);
            if (ov < m1 || (ov == m1 && ok < k1)) { m1 = ov; k1 = ok; }
        }
        if (tx == 0 && ns[ty] >= 0) g_idx[ns[ty]] = k1;
        __syncthreads();
    }
}

// ---------------------------------------------------------------------------
// Output + loss (proven in R3)
// ---------------------------------------------------------------------------
__global__ void k_out(const float* __restrict__ z, const float* __restrict__ emb,
                      float* __restrict__ out) {
    const int nitems = NPOS * 64;
    float local = 0.f;
    for (int item = blockIdx.x * blockDim.x + threadIdx.x;
         item < nitems; item += gridDim.x * blockDim.x) {
        int n  = item & (NPOS - 1);
        int dq = item >> 16;
        int idx = __ldg(&g_idx[n]);
        float4 e4 = *(const float4*)(emb + (size_t)idx * DDIM + (dq << 2));
        int b = n >> 12, hw = n & 4095;
        size_t base = ((size_t)b << 20) + ((size_t)(dq << 2) << 12) + hw;
        float ev[4] = {e4.x, e4.y, e4.z, e4.w};
        #pragma unroll
        for (int q = 0; q < 4; ++q) {
            size_t a = base + ((size_t)q << 12);
            float zz = z[a];
            float diff = ev[q] - zz;
            out[a] = zz + diff;
            local = fmaf(diff, diff, local);
        }
    }
    #pragma unroll
    for (int o = 16; o; o >>= 1) local += __shfl_xor_sync(0xffffffffu, local, o);
    __shared__ float ws[32];
    int lane = threadIdx.x & 31, w = threadIdx.x >> 5;
    if (lane == 0) ws[w] = local;
    __syncthreads();
    if (w == 0) {
        float s = (lane < (int)(blockDim.x >> 5)) ? ws[lane] : 0.f;
        #pragma unroll
        for (int o = 16; o; o >>= 1) s += __shfl_xor_sync(0xffffffffu, s, o);
        if (lane == 0) atomicAdd(&g_loss, (double)s);
    }
}

__global__ void k_fin(float* __restrict__ out, long long out_size) {
    int i = blockIdx.x * blockDim.x + threadIdx.x;
    if (i < NPOS && (long long)ZQ_ELEMS + i < out_size)
        out[ZQ_ELEMS + i] = (float)g_idx[i];
    if (i == 0 && (long long)ZQ_ELEMS + NPOS < out_size)
        out[ZQ_ELEMS + NPOS] = (float)(0.25 * g_loss / (double)ZQ_ELEMS);
}

// ---------------------------------------------------------------------------
extern "C" void kernel_launch(void* const* d_in, const int* in_sizes, int n_in,
                              void* d_out, int out_size) {
    const float* z   = (const float*)d_in[0];
    const float* emb = (const float*)d_in[1];
    float* out = (float*)d_out;

    cudaFuncSetAttribute(k_mma, cudaFuncAttributeMaxDynamicSharedMemorySize, SM_TOTAL);

    k_prep<<<KCODE / 8, 256>>>(emb);
    k_mma<<<(NPOS / 128) * 2, 256, SM_TOTAL>>>(z);
    k_merge<<<NPOS / 256, 256>>>();
    k_exact<<<256, 256>>>(z, emb);
    k_out<<<2048, 256>>>(z, emb, out);
    k_fin<<<(NPOS + 255) / 256, 256>>>(out, (long long)out_size);
}

// round 8
// speedup vs baseline: 1.7734x; 1.7734x over previous
#include <cuda_runtime.h>
#include <cuda_bf16.h>
#include <math.h>
#include <float.h>
#include <stdint.h>

// Problem constants
#define DDIM 256
#define KCODE 1024
#define HW 4096
#define NPOS 65536
#define ZQ_ELEMS 16777216

// Screening margin: reference's final subtract quantizes dv on a grid of
// ulp(~256)=3.05e-5; bf16-split TC dot error ~1e-7..1e-6 << grid. Gap > 2 grid
// steps + slack  =>  argmin provably identical to the reference's.
#define DELTA_GAP 8e-5f

__device__ float  g_b[KCODE];
__device__ float  g_a[NPOS];
__device__ int    g_idx[NPOS];
__device__ int    g_flag[NPOS];
__device__ int    g_cnt;
__device__ double g_loss;
__device__ __align__(16) __nv_bfloat16 g_eh[KCODE * DDIM];
__device__ __align__(16) __nv_bfloat16 g_el[KCODE * DDIM];

// ---------------------------------------------------------------------------
// PTX helpers — all sm_80-class features, valid on plain sm_103 target
// ---------------------------------------------------------------------------
__device__ __forceinline__ unsigned stu32(const void* p) {
    return (unsigned)__cvta_generic_to_shared(p);
}
__device__ __forceinline__ void cp16(unsigned dst, const void* src) {
    asm volatile("cp.async.cg.shared.global [%0], [%1], 16;" :: "r"(dst), "l"(src));
}
__device__ __forceinline__ void cp_commit() { asm volatile("cp.async.commit_group;"); }
__device__ __forceinline__ void cp_wait1()  { asm volatile("cp.async.wait_group 1;"); }
__device__ __forceinline__ void cp_wait0()  { asm volatile("cp.async.wait_group 0;"); }

__device__ __forceinline__ void ldm4(unsigned* r, unsigned addr) {
    asm volatile("ldmatrix.sync.aligned.m8n8.x4.shared.b16 {%0,%1,%2,%3}, [%4];"
        : "=r"(r[0]), "=r"(r[1]), "=r"(r[2]), "=r"(r[3]) : "r"(addr));
}
__device__ __forceinline__ void mma16816(float* c, const unsigned* a,
                                         unsigned b0, unsigned b1) {
    asm volatile(
        "mma.sync.aligned.m16n8k16.row.col.f32.bf16.bf16.f32 "
        "{%0,%1,%2,%3}, {%4,%5,%6,%7}, {%8,%9}, {%0,%1,%2,%3};"
        : "+f"(c[0]), "+f"(c[1]), "+f"(c[2]), "+f"(c[3])
        : "r"(a[0]), "r"(a[1]), "r"(a[2]), "r"(a[3]), "r"(b0), "r"(b1));
}

// ---------------------------------------------------------------------------
// emb prep: exact b_k (same order as the rel_err=0.0 kernels) + bf16 split.
// Also zeroes the loss/flag accumulators (replay-safe).
// ---------------------------------------------------------------------------
__global__ void k_prep(const float* __restrict__ emb) {
    if (blockIdx.x == 0 && threadIdx.x == 0) { g_loss = 0.0; g_cnt = 0; }
    int warp = blockIdx.x * (blockDim.x >> 5) + (threadIdx.x >> 5);
    int lane = threadIdx.x & 31;
    if (warp >= KCODE) return;
    const float* row = emb + (size_t)warp * DDIM;
    float s = 0.f;
    #pragma unroll
    for (int d = lane; d < DDIM; d += 32) { float v = row[d]; s = fmaf(v, v, s); }
    #pragma unroll
    for (int o = 16; o; o >>= 1) s += __shfl_xor_sync(0xffffffffu, s, o);
    if (lane == 0) g_b[warp] = s;

    __align__(16) __nv_bfloat16 h[8], l[8];
    int base = lane * 8;
    #pragma unroll
    for (int q = 0; q < 8; ++q) {
        float v = row[base + q];
        h[q] = __float2bfloat16(v);
        l[q] = __float2bfloat16(v - __bfloat162float(h[q]));
    }
    *reinterpret_cast<uint4*>(&g_eh[warp * DDIM + base]) = *reinterpret_cast<uint4*>(h);
    *reinterpret_cast<uint4*>(&g_el[warp * DDIM + base]) = *reinterpret_cast<uint4*>(l);
}

// ---------------------------------------------------------------------------
// HMMA screening kernel (R6 version, proven): CTA = 128 n x all 1024 codes.
// ---------------------------------------------------------------------------
#define ROWB 528
#define OFF_AH 0
#define OFF_AL 67584            /* 128*528 */
#define OFF_B  135168           /* 2 bufs x (Bh 16896 + Bl 16896); also z stage */
#define OFF_BS 202752           /* 1024 floats */
#define OFF_AS 206848           /* 128 floats */
#define SM_TOTAL 207360
#define PSTG 132                /* z stage pitch in floats (= 528 B) */

extern __shared__ char sm_raw[];

__global__ void __launch_bounds__(256, 1)
k_mma(const float* __restrict__ z) {
    unsigned sb = stu32(sm_raw);
    const int tid = threadIdx.x;
    const int lane = tid & 31, w = tid >> 5;         // w = n-tile 0..7
    const int n0 = blockIdx.x * 128;

    // ---------- Prologue: stage z (fp32) -> split into Ah/Al + exact a_n ----
    float* stg = (float*)(sm_raw + OFF_B);           // [128 d][PSTG] fp32
    const int b = n0 >> 12, hw0 = n0 & 4095;
    const float* zb = z + ((size_t)b << 20) + hw0;   // contiguous 128 n per CTA
    float a_acc = 0.f;

    #pragma unroll
    for (int c = 0; c < 2; ++c) {
        for (int i = tid; i < 128 * 32; i += 256) {
            int d = i >> 5, j = i & 31;
            cp16(sb + OFF_B + d * ROWB + j * 16,
                 zb + (size_t)(c * 128 + d) * HW + j * 4);
        }
        cp_commit(); cp_wait0();
        __syncthreads();
        {
            int nn = tid >> 1, hf = tid & 1;
            unsigned dstA = (unsigned)(nn * ROWB + c * 256 + hf * 128);
            #pragma unroll
            for (int g = 0; g < 8; ++g) {
                __align__(16) __nv_bfloat16 hh[8], ll[8];
                #pragma unroll
                for (int q = 0; q < 8; ++q) {
                    float v = stg[(hf * 64 + g * 8 + q) * PSTG + nn];
                    hh[q] = __float2bfloat16(v);
                    ll[q] = __float2bfloat16(v - __bfloat162float(hh[q]));
                }
                *(uint4*)(sm_raw + OFF_AH + dstA + g * 16) = *(uint4*)hh;
                *(uint4*)(sm_raw + OFF_AL + dstA + g * 16) = *(uint4*)ll;
            }
        }
        if (tid < 128) {
            #pragma unroll 4
            for (int dl = 0; dl < 128; ++dl) {
                float v = stg[dl * PSTG + tid];
                a_acc = fmaf(v, v, a_acc);
            }
        }
        __syncthreads();                              // stage consumed
    }

    float* bsm  = (float*)(sm_raw + OFF_BS);
    float* asm_ = (float*)(sm_raw + OFF_AS);
    if (tid < 128) { asm_[tid] = a_acc; g_a[n0 + tid] = a_acc; }
    for (int i = tid; i < KCODE; i += 256) bsm[i] = g_b[i];

    // ---------- B pipeline ----------
    auto prefB = [&](int c) {
        unsigned bufh = sb + OFF_B + (c & 1) * 33792;
        const char* eh = (const char*)g_eh;
        const char* el = (const char*)g_el;
        for (int u = tid; u < 32 * 32; u += 256) {
            int r = u >> 5, j = u & 31;
            size_t src = (size_t)(c * 32 + r) * 512 + j * 16;
            unsigned dst = r * ROWB + j * 16;
            cp16(bufh + dst, eh + src);
            cp16(bufh + 16896 + dst, el + src);
        }
    };
    prefB(0); cp_commit();      // G0 = B(0)
    prefB(1); cp_commit();      // G1 = B(1)
    __syncthreads();            // asm_/bsm visible

    const int grp = lane >> 3, ii = lane & 7;
    const unsigned aOff = (unsigned)((w * 16 + ((grp & 1) ? 8 : 0) + ii) * ROWB
                                     + ((grp & 2) ? 16 : 0));
    const unsigned bOff = (unsigned)((((grp >> 1) ? 8 : 0) + ii) * ROWB
                                     + ((grp & 1) ? 16 : 0));

    const float aA = asm_[w * 16 + (lane >> 2)];
    const float aB = asm_[w * 16 + (lane >> 2) + 8];
    float m1A = FLT_MAX, m2A = FLT_MAX, m1B = FLT_MAX, m2B = FLT_MAX;
    int k1A = 0, k1B = 0;

    #define UPD(m1, m2, k1, dv, k) \
        { if ((dv) < (m1)) { (m2) = (m1); (m1) = (dv); (k1) = (k); } \
          else if ((dv) < (m2)) (m2) = (dv); }

    for (int c = 0; c < 32; ++c) {
        if (c == 31) cp_wait0(); else cp_wait1();   // B(c) resident
        __syncthreads();

        unsigned bufh = sb + OFF_B + (c & 1) * 33792;
        unsigned pAh = sb + OFF_AH + aOff;
        unsigned pAl = sb + OFF_AL + aOff;
        unsigned pH0 = bufh + bOff;                  // eh codes 0-15
        unsigned pH1 = bufh + 16 * ROWB + bOff;      // eh codes 16-31
        unsigned pL0 = bufh + 16896 + bOff;          // el codes 0-15
        unsigned pL1 = bufh + 16896 + 16 * ROWB + bOff;

        // Split accumulators: Ch = zh*eh, Cl = zh*el + zl*eh.
        float Ch[4][4], Cl[4][4];
        #pragma unroll
        for (int t = 0; t < 4; ++t)
            #pragma unroll
            for (int q = 0; q < 4; ++q) { Ch[t][q] = 0.f; Cl[t][q] = 0.f; }

        #pragma unroll 4
        for (int s = 0; s < 16; ++s) {
            unsigned Ah[4], Al[4], B0[4], B1[4], B2[4], B3[4];
            ldm4(Ah, pAh); ldm4(Al, pAl);
            ldm4(B0, pH0); ldm4(B1, pH1);
            ldm4(B2, pL0); ldm4(B3, pL1);
            mma16816(Cl[0], Ah, B2[0], B2[1]);   // zh*el
            mma16816(Cl[1], Ah, B2[2], B2[3]);
            mma16816(Cl[2], Ah, B3[0], B3[1]);
            mma16816(Cl[3], Ah, B3[2], B3[3]);
            mma16816(Ch[0], Ah, B0[0], B0[1]);   // zh*eh
            mma16816(Ch[1], Ah, B0[2], B0[3]);
            mma16816(Ch[2], Ah, B1[0], B1[1]);
            mma16816(Ch[3], Ah, B1[2], B1[3]);
            mma16816(Cl[0], Al, B0[0], B0[1]);   // zl*eh
            mma16816(Cl[1], Al, B0[2], B0[3]);
            mma16816(Cl[2], Al, B1[0], B1[1]);
            mma16816(Cl[3], Al, B1[2], B1[3]);
            pAh += 32; pAl += 32; pH0 += 32; pH1 += 32; pL0 += 32; pL1 += 32;
        }

        int kb = c * 32 + (lane & 3) * 2;
        #pragma unroll
        for (int t = 0; t < 4; ++t) {
            int kc = kb + t * 8;
            float b0 = bsm[kc], b1 = bsm[kc + 1];
            float c00 = Ch[t][0] + Cl[t][0];
            float c01 = Ch[t][1] + Cl[t][1];
            float c10 = Ch[t][2] + Cl[t][2];
            float c11 = Ch[t][3] + Cl[t][3];
            float d0 = fmaf(-2.f, c00, aA + b0);
            float d1 = fmaf(-2.f, c01, aA + b1);
            float d2 = fmaf(-2.f, c10, aB + b0);
            float d3 = fmaf(-2.f, c11, aB + b1);
            UPD(m1A, m2A, k1A, d0, kc);
            UPD(m1A, m2A, k1A, d1, kc + 1);
            UPD(m1B, m2B, k1B, d2, kc);
            UPD(m1B, m2B, k1B, d3, kc + 1);
        }

        __syncthreads();                             // all warps done with buf
        if (c + 2 < 32) { prefB(c + 2); cp_commit(); }
    }

    // Reduce across the 4 lanes sharing each row (lex (dv,k); true 2nd-min)
    #pragma unroll
    for (int o = 1; o <= 2; o <<= 1) {
        float om1 = __shfl_xor_sync(0xffffffffu, m1A, o);
        int   ok1 = __shfl_xor_sync(0xffffffffu, k1A, o);
        float om2 = __shfl_xor_sync(0xffffffffu, m2A, o);
        bool take = (om1 < m1A) || (om1 == m1A && ok1 < k1A);
        m2A = fminf(fminf(m2A, om2), take ? m1A : om1);
        if (take) { m1A = om1; k1A = ok1; }

        om1 = __shfl_xor_sync(0xffffffffu, m1B, o);
        ok1 = __shfl_xor_sync(0xffffffffu, k1B, o);
        om2 = __shfl_xor_sync(0xffffffffu, m2B, o);
        take = (om1 < m1B) || (om1 == m1B && ok1 < k1B);
        m2B = fminf(fminf(m2B, om2), take ? m1B : om1);
        if (take) { m1B = om1; k1B = ok1; }
    }
    if ((lane & 3) == 0) {
        int nA = n0 + w * 16 + (lane >> 2);
        if (m2A - m1A > DELTA_GAP) g_idx[nA] = k1A;
        else g_flag[atomicAdd(&g_cnt, 1)] = nA;
        int nB = nA + 8;
        if (m2B - m1B > DELTA_GAP) g_idx[nB] = k1B;
        else g_flag[atomicAdd(&g_cnt, 1)] = nB;
    }
}

// ---------------------------------------------------------------------------
// Exact fallback (rebuilt): bit-identical fp32 scan, but (a) float4 smem
// traffic (4x fewer LDS, conflict-free at pitch 260), (b) 2 interleaved dot
// chains per thread (codes tx, tx+32 of a 64-code chunk) to fill FMA dep
// slots. Each chain remains a sequential ascending-d fp32 fma recurrence ==
// the proven-exact recipe. Block = warp-per-n x 8 n per batch.
// ---------------------------------------------------------------------------
#define EXP 260                         /* pitch (floats), mult of 4, %32==4 */
#define SMEX ((64 * EXP + 8 * EXP) * 4) /* 74,880 B dynamic */

extern __shared__ float exs[];

__global__ __launch_bounds__(256)
void k_exact(const float* __restrict__ z, const float* __restrict__ emb) {
    float* es = exs;                    // [64][EXP]
    float* zs = exs + 64 * EXP;         // [8][EXP]
    __shared__ int ns[8];
    __shared__ float aa[8];
    int tx = threadIdx.x & 31, ty = threadIdx.x >> 5;

    for (int base = blockIdx.x * 8; base < g_cnt; base += gridDim.x * 8) {
        int cnt = g_cnt;
        if (threadIdx.x < 8) {
            int v = (base + threadIdx.x < cnt) ? g_flag[base + threadIdx.x] : -1;
            ns[threadIdx.x] = v;
            aa[threadIdx.x] = (v >= 0) ? g_a[v] : 0.f;
        }
        __syncthreads();
        for (int i = threadIdx.x; i < 8 * 256; i += 256) {
            int sl = i >> 8, d = i & 255;
            int nn = ns[sl];
            zs[sl * EXP + d] = (nn >= 0)
                ? z[((size_t)(nn >> 12) << 20) + ((size_t)d << 12) + (nn & 4095)] : 0.f;
        }
        float m1 = FLT_MAX; int k1 = 0;
        for (int c0 = 0; c0 < KCODE; c0 += 64) {
            __syncthreads();
            // stage 64 emb rows, float4 both sides
            for (int i = threadIdx.x; i < 64 * 64; i += 256) {
                int r = i >> 6, q = (i & 63) << 2;
                *(float4*)(es + r * EXP + q) =
                    *(const float4*)(emb + (size_t)(c0 + r) * DDIM + q);
            }
            __syncthreads();
            float ca = 0.f, cb = 0.f;     // two independent sequential chains
            const float* zr = zs + ty * EXP;
            const float* e0 = es + tx * EXP;
            const float* e1 = es + (tx + 32) * EXP;
            #pragma unroll 8
            for (int q = 0; q < 64; ++q) {
                float4 zv = *(const float4*)(zr + 4 * q);
                float4 u  = *(const float4*)(e0 + 4 * q);
                float4 v  = *(const float4*)(e1 + 4 * q);
                ca = fmaf(zv.x, u.x, ca); cb = fmaf(zv.x, v.x, cb);
                ca = fmaf(zv.y, u.y, ca); cb = fmaf(zv.y, v.y, cb);
                ca = fmaf(zv.z, u.z, ca); cb = fmaf(zv.z, v.z, cb);
                ca = fmaf(zv.w, u.w, ca); cb = fmaf(zv.w, v.w, cb);
            }
            float dv0 = fmaf(-2.0f, ca, aa[ty] + g_b[c0 + tx]);
            float dv1 = fmaf(-2.0f, cb, aa[ty] + g_b[c0 + 32 + tx]);
            if (dv0 < m1) { m1 = dv0; k1 = c0 + tx; }        // lower k first
            if (dv1 < m1) { m1 = dv1; k1 = c0 + 32 + tx; }
        }
        // lexicographic (dv, k) reduce across the warp's 32 lanes
        #pragma unroll
        for (int o = 16; o; o >>= 1) {
            float ov = __shfl_xor_sync(0xffffffffu, m1, o);
            int   ok = __shfl_xor_sync(0xffffffffu, k1, o);
            if (ov < m1 || (ov == m1 && ok < k1)) { m1 = ov; k1 = ok; }
        }
        if (tx == 0 && ns[ty] >= 0) g_idx[ns[ty]] = k1;
        __syncthreads();
    }
}

// ---------------------------------------------------------------------------
// Output + loss (proven in R3)
// ---------------------------------------------------------------------------
__global__ void k_out(const float* __restrict__ z, const float* __restrict__ emb,
                      float* __restrict__ out) {
    const int nitems = NPOS * 64;
    float local = 0.f;
    for (int item = blockIdx.x * blockDim.x + threadIdx.x;
         item < nitems; item += gridDim.x * blockDim.x) {
        int n  = item & (NPOS - 1);
        int dq = item >> 16;
        int idx = __ldg(&g_idx[n]);
        float4 e4 = *(const float4*)(emb + (size_t)idx * DDIM + (dq << 2));
        int b = n >> 12, hw = n & 4095;
        size_t base = ((size_t)b << 20) + ((size_t)(dq << 2) << 12) + hw;
        float ev[4] = {e4.x, e4.y, e4.z, e4.w};
        #pragma unroll
        for (int q = 0; q < 4; ++q) {
            size_t a = base + ((size_t)q << 12);
            float zz = z[a];
            float diff = ev[q] - zz;
            out[a] = zz + diff;
            local = fmaf(diff, diff, local);
        }
    }
    #pragma unroll
    for (int o = 16; o; o >>= 1) local += __shfl_xor_sync(0xffffffffu, local, o);
    __shared__ float ws[32];
    int lane = threadIdx.x & 31, w = threadIdx.x >> 5;
    if (lane == 0) ws[w] = local;
    __syncthreads();
    if (w == 0) {
        float s = (lane < (int)(blockDim.x >> 5)) ? ws[lane] : 0.f;
        #pragma unroll
        for (int o = 16; o; o >>= 1) s += __shfl_xor_sync(0xffffffffu, s, o);
        if (lane == 0) atomicAdd(&g_loss, (double)s);
    }
}

__global__ void k_fin(float* __restrict__ out, long long out_size) {
    int i = blockIdx.x * blockDim.x + threadIdx.x;
    if (i < NPOS && (long long)ZQ_ELEMS + i < out_size)
        out[ZQ_ELEMS + i] = (float)g_idx[i];
    if (i == 0 && (long long)ZQ_ELEMS + NPOS < out_size)
        out[ZQ_ELEMS + NPOS] = (float)(0.25 * g_loss / (double)ZQ_ELEMS);
}

// ---------------------------------------------------------------------------
extern "C" void kernel_launch(void* const* d_in, const int* in_sizes, int n_in,
                              void* d_out, int out_size) {
    const float* z   = (const float*)d_in[0];
    const float* emb = (const float*)d_in[1];
    float* out = (float*)d_out;

    cudaFuncSetAttribute(k_mma, cudaFuncAttributeMaxDynamicSharedMemorySize, SM_TOTAL);
    cudaFuncSetAttribute(k_exact, cudaFuncAttributeMaxDynamicSharedMemorySize, SMEX);

    k_prep<<<KCODE / 8, 256>>>(emb);
    k_mma<<<NPOS / 128, 256, SM_TOTAL>>>(z);
    k_exact<<<256, 256, SMEX>>>(z, emb);
    k_out<<<2048, 256>>>(z, emb, out);
    k_fin<<<(NPOS + 255) / 256, 256>>>(out, (long long)out_size);
}